// round 15
// baseline (speedup 1.0000x reference)
#include <cuda_runtime.h>
#include <cuda_fp16.h>
#include <cstdint>
#include <math.h>

// SpatialGRU: B=256, C=128, L1=L2=32, U=128
// R14 + k1 M-split: BOTH kernels use 64x128x512 tiles (512 thr, 4x4 warp grid,
// 16x32 warp tiles, 56-reg footprint -> 2 blocks/SM co-residency on wide diags).
// PDL with pre-wait MMA iters retained.

#define NP  1024
#define BSZ 256
#define NTHR 512

// ---- device scratch (no allocation allowed) ----
__device__ __half g_Th [NP * BSZ * 128];  // s, fp16 (MMA operand)
__device__ float  g_H  [NP * BSZ * 128];  // h, fp32 (epilogue operand)
__device__ __half g_Hr [NP * BSZ * 128];  // h, fp16 (MMA operand)
__device__ __half g_WpT[896 * 512];       // W^T col-permuted, [n][k]
__device__ __half g_U2T[128 * 512];       // [Umat;w_ij]^T, [n][k]
__device__ float  g_bP [896];             // permuted bias
__device__ __half g_A2 [8192 * 384];      // GEMM2 A (r*h parts)
__device__ float  g_Z  [8192 * 512];      // softmaxed gates [m][u*4+g]

__device__ __forceinline__ void mma16(float* c, const uint32_t* a, uint32_t b0, uint32_t b1) {
    asm volatile("mma.sync.aligned.m16n8k16.row.col.f32.f16.f16.f32 "
        "{%0,%1,%2,%3},{%4,%5,%6,%7},{%8,%9},{%0,%1,%2,%3};"
        : "+f"(c[0]), "+f"(c[1]), "+f"(c[2]), "+f"(c[3])
        : "r"(a[0]), "r"(a[1]), "r"(a[2]), "r"(a[3]), "r"(b0), "r"(b1));
}
__device__ __forceinline__ void cp16(uint32_t dst, const void* src, int sz) {
    asm volatile("cp.async.cg.shared.global [%0], [%1], 16, %2;" :: "r"(dst), "l"(src), "r"(sz));
}
__device__ __forceinline__ void ldsm4(uint32_t* r, uint32_t a) {
    asm volatile("ldmatrix.sync.aligned.m8n8.x4.shared.b16 {%0,%1,%2,%3}, [%4];"
        : "=r"(r[0]), "=r"(r[1]), "=r"(r[2]), "=r"(r[3]) : "r"(a));
}
__device__ __forceinline__ void ldsm2(uint32_t* r, uint32_t a) {
    asm volatile("ldmatrix.sync.aligned.m8n8.x2.shared.b16 {%0,%1}, [%2];"
        : "=r"(r[0]), "=r"(r[1]) : "r"(a));
}
__device__ __forceinline__ void pdl_wait() {
    asm volatile("griddepcontrol.wait;" ::: "memory");
}
__device__ __forceinline__ void pdl_trigger() {
    asm volatile("griddepcontrol.launch_dependents;" ::: "memory");
}

// ---------------------------------------------------------------------------
// setup (2 launches)
__global__ void transpose_kernel(const float* __restrict__ in) {
    __shared__ float tile[32][33];
    int x  = blockIdx.x * 32 + threadIdx.x;   // p
    int y0 = blockIdx.y * 32;                 // bc
#pragma unroll
    for (int r = 0; r < 4; r++) {
        int y = y0 + threadIdx.y + r * 8;
        tile[threadIdx.y + r * 8][threadIdx.x] = in[(size_t)y * 1024 + x];
    }
    __syncthreads();
    int xo  = blockIdx.y * 32 + threadIdx.x;
    int yo0 = blockIdx.x * 32;
#pragma unroll
    for (int r = 0; r < 4; r++) {
        int yo = yo0 + threadIdx.y + r * 8;
        g_Th[(size_t)yo * 32768 + xo] = __float2half_rn(tile[threadIdx.x][threadIdx.y + r * 8]);
    }
}

#define NWT (896 * 512)
#define NUT (128 * 512)
__global__ void prep_all_kernel(const float* __restrict__ W, const float* __restrict__ Umat,
                                const float* __restrict__ w_ij, const float* __restrict__ bias) {
    int idx = blockIdx.x * 256 + threadIdx.x;
    if (idx < NWT) {
        int n = idx >> 9, k = idx & 511;
        int corig = (n < 384) ? n : 384 + ((n - 384) & 3) * 128 + ((n - 384) >> 2);
        g_WpT[idx] = __float2half_rn(W[(size_t)k * 896 + corig]);
    } else if (idx < NWT + NUT) {
        int t = idx - NWT;
        int n = t >> 9, k = t & 511;
        g_U2T[t] = __float2half_rn((k < 384) ? Umat[k * 128 + n] : w_ij[(k - 384) * 128 + n]);
    } else if (idx < NWT + NUT + 896) {
        int c = idx - NWT - NUT;
        if (c < 384) g_bP[c] = bias[c];
        else {
            int cc = c - 384, u = cc >> 2, g = cc & 3;
            g_bP[c] = bias[384 + g * 128 + u];
        }
    }
}

// ---------------------------------------------------------------------------
// shared tile geometry: A = 64 x 64 halves staged, B = 128 x 64 halves
#define STRH   72
#define AHALF  (64 * STRH)
#define STGH   (AHALF + 128 * STRH)
#define SMEMB  (2 * STGH * 2)           // 55296 bytes

// 16x32 warp tiles: one ldsm4 (A), 4x ldsm2 (B), 16 HMMA per k-tile
#define MMA_TILE(aB_)  do {                                                     \
        const uint32_t bBv_ = (aB_) + AHALF * 2;                                \
        _Pragma("unroll")                                                       \
        for (int k16 = 0; k16 < 4; k16++) {                                     \
            const uint32_t kb2 = k16 * 32;                                      \
            uint32_t af[4];                                                     \
            ldsm4(af, (aB_) + aOff0 + kb2);                                     \
            _Pragma("unroll")                                                   \
            for (int nt = 0; nt < 4; nt++) {                                    \
                uint32_t bf[2];                                                 \
                ldsm2(bf, bBv_ + bOff + nt * (8 * STRH * 2) + kb2);             \
                mma16(acc[nt], af, bf[0], bf[1]);                               \
            }                                                                   \
        }                                                                       \
    } while (0)

// K1: rz = q @ Wp ; gate epilogue. grid = (7 ntiles, nc*4 mtiles of 64), 512 thr.
// K-order permuted: stages 0,1 = s_ij segment (independent of recurrence).
__global__ __launch_bounds__(NTHR) void k1_kernel(int d) {
    extern __shared__ __half sm[];
    const uint32_t smA0 = (uint32_t)__cvta_generic_to_shared(sm);

    const int tid = threadIdx.x, lane = tid & 31, warp = tid >> 5;
    const int wm = warp >> 2, wn = warp & 3, qj = lane & 3, ql = lane >> 2;
    const int i0 = (d > 31) ? d - 31 : 0;
    const int Mbase = blockIdx.y * 64;
    const int cell = Mbase >> 8, b0 = Mbase & 255;
    const int i = i0 + cell, j = d - i, p = i * 32 + j;
    const int nc0 = blockIdx.x * 128;

    const int l15 = lane & 15, lhi = lane >> 4;
    const uint32_t aOff0 = ((wm * 16 + l15) * STRH + lhi * 8) * 2;
    const uint32_t bOff  = ((wn * 32 + (lane & 7)) * STRH + ((lane >> 3) & 1) * 8) * 2;

    const __half* src[4]; int vld[4];
    vld[0] = (i > 0) ? 16 : 0;
    vld[1] = (j > 0) ? 16 : 0;
    vld[2] = (i > 0 && j > 0) ? 16 : 0;
    vld[3] = 16;
    src[0] = vld[0] ? g_Hr + ((size_t)(p - 32) * BSZ + b0) * 128 : g_Th;
    src[1] = vld[1] ? g_Hr + ((size_t)(p - 1 ) * BSZ + b0) * 128 : g_Th;
    src[2] = vld[2] ? g_Hr + ((size_t)(p - 33) * BSZ + b0) * 128 : g_Th;
    src[3] = g_Th + ((size_t)p * BSZ + b0) * 128;

    float acc[4][4] = {};

    // stage t: seg = (t>>1)==0 ? 3 : (t>>1)-1 ; k_off within seg = (t&1)*64
#define STAGE1(t, buf) do {                                                     \
        int ps_ = (t) >> 1;                                                     \
        int seg_ = (ps_ == 0) ? 3 : ps_ - 1;                                    \
        const __half* sp_ = src[seg_]; int v_ = vld[seg_];                      \
        int kof_ = ((t) & 1) * 64;                                              \
        uint32_t aB_ = smA0 + (buf) * (STGH * 2);                               \
        uint32_t bB_ = aB_ + AHALF * 2;                                         \
        {                                                                       \
            int m_ = tid >> 3, c_ = tid & 7;                                    \
            cp16(aB_ + (m_ * STRH + c_ * 8) * 2,                                \
                 sp_ + (size_t)m_ * 128 + kof_ + c_ * 8, v_);                   \
        }                                                                       \
        const __half* wp_ = g_WpT + (size_t)nc0 * 512 + seg_ * 128 + kof_;      \
        _Pragma("unroll")                                                       \
        for (int r_ = 0; r_ < 2; r_++) {                                        \
            int ix_ = tid + r_ * NTHR;                                          \
            int n_ = ix_ >> 3, c_ = ix_ & 7;                                    \
            cp16(bB_ + (n_ * STRH + c_ * 8) * 2,                                \
                 wp_ + (size_t)n_ * 512 + c_ * 8, 16);                          \
        }                                                                       \
        asm volatile("cp.async.commit_group;");                                 \
    } while (0)

    STAGE1(0, 0);
    STAGE1(1, 1);
    asm volatile("cp.async.wait_group 1;");
    __syncthreads();
    MMA_TILE(smA0);                               // iter 0 (buf 0)
    asm volatile("cp.async.wait_group 0;");
    __syncthreads();
    MMA_TILE(smA0 + STGH * 2);                    // iter 1 (buf 1)
    pdl_wait();
    __syncthreads();
    STAGE1(2, 0);
    STAGE1(3, 1);
#pragma unroll 1
    for (int t = 2; t < 8; t++) {
        if (t < 7) asm volatile("cp.async.wait_group 1;");
        else       asm volatile("cp.async.wait_group 0;");
        __syncthreads();
        const uint32_t aB = smA0 + (t & 1) * (STGH * 2);
        MMA_TILE(aB);
        __syncthreads();
        if (t < 6) STAGE1(t + 2, t & 1);
    }
    pdl_trigger();

    // ---- epilogue ----
    if (nc0 < 384) {
        const float* hsrc[3];
        hsrc[0] = (j > 0)          ? g_H + ((size_t)(p - 1 ) * BSZ + b0) * 128 : nullptr;
        hsrc[1] = (i > 0)          ? g_H + ((size_t)(p - 32) * BSZ + b0) * 128 : nullptr;
        hsrc[2] = (i > 0 && j > 0) ? g_H + ((size_t)(p - 33) * BSZ + b0) * 128 : nullptr;
#pragma unroll
        for (int half = 0; half < 2; half++) {
            int lr = wm * 16 + ql + half * 8;
            int Mr = Mbase + lr;
#pragma unroll
            for (int nt = 0; nt < 4; nt++) {
                int c = nc0 + wn * 32 + nt * 8 + 2 * qj;
                float v0 = acc[nt][half * 2 + 0] + g_bP[c];
                float v1 = acc[nt][half * 2 + 1] + g_bP[c + 1];
                v0 = fminf(fmaxf(0.2f * v0 + 0.5f, 0.f), 1.f);
                v1 = fminf(fmaxf(0.2f * v1 + 0.5f, 0.f), 1.f);
                int seg = c >> 7, u = c & 127;
                const float* hp = hsrc[seg];
                float h0 = hp ? hp[lr * 128 + u]     : 0.f;
                float h1 = hp ? hp[lr * 128 + u + 1] : 0.f;
                *(__half2*)&g_A2[(size_t)Mr * 384 + c] =
                    __floats2half2_rn(v0 * h0, v1 * h1);
            }
        }
    } else {
#pragma unroll
        for (int half = 0; half < 2; half++) {
            int lr = wm * 16 + ql + half * 8;
            int Mr = Mbase + lr;
#pragma unroll
            for (int nt = 0; nt < 4; nt++) {
                int c = nc0 + wn * 32 + nt * 8 + 2 * qj;
                float z0 = acc[nt][half * 2 + 0] + g_bP[c];
                float z1 = acc[nt][half * 2 + 1] + g_bP[c + 1];
                float q0 = __shfl_xor_sync(0xffffffffu, z0, 1);
                float q1 = __shfl_xor_sync(0xffffffffu, z1, 1);
                float mx = fmaxf(fmaxf(z0, z1), fmaxf(q0, q1));
                float e0 = __expf(z0 - mx), e1 = __expf(z1 - mx);
                float s2 = e0 + e1;
                float st = s2 + __shfl_xor_sync(0xffffffffu, s2, 1);
                float inv = 1.f / st;
                int cc = c - 384, u = cc >> 2, g = cc & 3;
                *(float2*)&g_Z[(size_t)Mr * 512 + u * 4 + g] =
                    make_float2(e0 * inv, e1 * inv);
            }
        }
    }
}

// ---------------------------------------------------------------------------
// K2: 64x128x512 tiles, grid = nc*4, 512 thr (same geometry as k1).
__global__ __launch_bounds__(NTHR) void k2_kernel(int d, const float* __restrict__ bias,
                                                  float* __restrict__ out) {
    extern __shared__ __half sm[];
    const uint32_t smA0 = (uint32_t)__cvta_generic_to_shared(sm);

    const int tid = threadIdx.x, lane = tid & 31, warp = tid >> 5;
    const int wm = warp >> 2, wn = warp & 3, qj = lane & 3, ql = lane >> 2;
    const int i0 = (d > 31) ? d - 31 : 0;
    const int Mbase = blockIdx.x * 64;
    const int cell = Mbase >> 8, b0 = Mbase & 255;
    const int i = i0 + cell, j = d - i, p = i * 32 + j;

    const int l15 = lane & 15, lhi = lane >> 4;
    const uint32_t aOff0 = ((wm * 16 + l15) * STRH + lhi * 8) * 2;
    const uint32_t bOff  = ((wn * 32 + (lane & 7)) * STRH + ((lane >> 3) & 1) * 8) * 2;

    const __half* Tsrc = g_Th + ((size_t)p * BSZ + b0) * 128;
    float acc[4][4] = {};

    // stage t: t<2 -> Tsrc k_off t*64, U2T rows 384+t*64 ; t>=2 -> A2 (t-2)*64
#define STAGE2(t, buf) do {                                                     \
        uint32_t aB_ = smA0 + (buf) * (STGH * 2);                               \
        uint32_t bB_ = aB_ + AHALF * 2;                                         \
        {                                                                       \
            int m_ = tid >> 3, c_ = tid & 7;                                    \
            const __half* sp_;                                                  \
            if ((t) < 2) sp_ = Tsrc + (size_t)m_ * 128 + (t) * 64 + c_ * 8;             \
            else         sp_ = g_A2 + (size_t)(Mbase + m_) * 384 + ((t) - 2) * 64 + c_ * 8; \
            cp16(aB_ + (m_ * STRH + c_ * 8) * 2, sp_, 16);                      \
        }                                                                       \
        const __half* up_ = g_U2T + (((t) < 2) ? (384 + (t) * 64) : (((t) - 2) * 64)); \
        _Pragma("unroll")                                                       \
        for (int r_ = 0; r_ < 2; r_++) {                                        \
            int ix_ = tid + r_ * NTHR;                                          \
            int n_ = ix_ >> 3, c_ = ix_ & 7;                                    \
            cp16(bB_ + (n_ * STRH + c_ * 8) * 2,                                \
                 up_ + (size_t)n_ * 512 + c_ * 8, 16);                          \
        }                                                                       \
        asm volatile("cp.async.commit_group;");                                 \
    } while (0)

    STAGE2(0, 0);
    STAGE2(1, 1);
    asm volatile("cp.async.wait_group 1;");
    __syncthreads();
    MMA_TILE(smA0);                               // iter 0 (buf 0)
    asm volatile("cp.async.wait_group 0;");
    __syncthreads();
    MMA_TILE(smA0 + STGH * 2);                    // iter 1 (buf 1)
    pdl_wait();
    __syncthreads();
    STAGE2(2, 0);
    STAGE2(3, 1);
#pragma unroll 1
    for (int t = 2; t < 8; t++) {
        if (t < 7) asm volatile("cp.async.wait_group 1;");
        else       asm volatile("cp.async.wait_group 0;");
        __syncthreads();
        const uint32_t aB = smA0 + (t & 1) * (STGH * 2);
        MMA_TILE(aB);
        __syncthreads();
        if (t < 6) STAGE2(t + 2, t & 1);
    }
    pdl_trigger();

    const float* hL = (j > 0)          ? g_H + ((size_t)(p - 1 ) * BSZ + b0) * 128 : nullptr;
    const float* hT = (i > 0)          ? g_H + ((size_t)(p - 32) * BSZ + b0) * 128 : nullptr;
    const float* hD = (i > 0 && j > 0) ? g_H + ((size_t)(p - 33) * BSZ + b0) * 128 : nullptr;
    float*  Hd  = g_H  + ((size_t)p * BSZ + b0) * 128;
    __half* Hrd = g_Hr + ((size_t)p * BSZ + b0) * 128;

#pragma unroll
    for (int half = 0; half < 2; half++) {
        int lr = wm * 16 + ql + half * 8;
        int Mr = Mbase + lr;
#pragma unroll
        for (int nt = 0; nt < 4; nt++) {
            int u = wn * 32 + nt * 8 + 2 * qj;
            float a0 = acc[nt][half * 2 + 0] + bias[896 + u];
            float a1 = acc[nt][half * 2 + 1] + bias[896 + u + 1];
            float hs0 = tanhf(a0), hs1 = tanhf(a1);
            float4 z0 = *(const float4*)&g_Z[(size_t)Mr * 512 + u * 4];
            float4 z1 = *(const float4*)&g_Z[(size_t)Mr * 512 + (u + 1) * 4];
            float l0 = hL ? hL[lr * 128 + u] : 0.f, l1 = hL ? hL[lr * 128 + u + 1] : 0.f;
            float t0 = hT ? hT[lr * 128 + u] : 0.f, t1 = hT ? hT[lr * 128 + u + 1] : 0.f;
            float d0 = hD ? hD[lr * 128 + u] : 0.f, d1 = hD ? hD[lr * 128 + u + 1] : 0.f;
            float h0 = z0.y * l0 + z0.z * t0 + z0.w * d0 + z0.x * hs0;
            float h1 = z1.y * l1 + z1.z * t1 + z1.w * d1 + z1.x * hs1;
            *(float2*)&Hd[lr * 128 + u]   = make_float2(h0, h1);
            *(__half2*)&Hrd[lr * 128 + u] = __floats2half2_rn(h0, h1);
            if (p == 1023)
                *(float2*)&out[(size_t)(b0 + lr) * 128 + u] = make_float2(h0, h1);
        }
    }
}

// ---------------------------------------------------------------------------
extern "C" void kernel_launch(void* const* d_in, const int* in_sizes, int n_in,
                              void* d_out, int out_size) {
    const float* inputs = (const float*)d_in[0];
    const float* W      = (const float*)d_in[1];
    const float* Umat   = (const float*)d_in[2];
    const float* bias   = (const float*)d_in[3];
    const float* w_ij   = (const float*)d_in[4];
    float* out = (float*)d_out;

    cudaFuncSetAttribute(k1_kernel, cudaFuncAttributeMaxDynamicSharedMemorySize, SMEMB);
    cudaFuncSetAttribute(k2_kernel, cudaFuncAttributeMaxDynamicSharedMemorySize, SMEMB);

    transpose_kernel<<<dim3(32, 1024), dim3(32, 8)>>>(inputs);
    prep_all_kernel<<<(NWT + NUT + 896 + 255) / 256, 256>>>(W, Umat, w_ij, bias);

    cudaLaunchAttribute attrs[1];
    attrs[0].id = cudaLaunchAttributeProgrammaticStreamSerialization;
    attrs[0].val.programmaticStreamSerializationAllowed = 1;

    for (int d = 0; d <= 62; d++) {
        int i0 = (d > 31) ? d - 31 : 0;
        int i1 = (d < 31) ? d : 31;
        int nc = i1 - i0 + 1;

        if (d == 0) {
            k1_kernel<<<dim3(7, nc * 4), NTHR, SMEMB>>>(d);
        } else {
            cudaLaunchConfig_t c1 = {};
            c1.gridDim = dim3(7, nc * 4); c1.blockDim = dim3(NTHR);
            c1.dynamicSmemBytes = SMEMB; c1.stream = 0;
            c1.attrs = attrs; c1.numAttrs = 1;
            cudaLaunchKernelEx(&c1, k1_kernel, d);
        }
        cudaLaunchConfig_t c2 = {};
        c2.gridDim = dim3(nc * 4); c2.blockDim = dim3(NTHR);
        c2.dynamicSmemBytes = SMEMB; c2.stream = 0;
        c2.attrs = attrs; c2.numAttrs = 1;
        cudaLaunchKernelEx(&c2, k2_kernel, d, bias, out);
    }
    (void)in_sizes; (void)n_in; (void)out_size;
}

// round 16
// speedup vs baseline: 1.0778x; 1.0778x over previous
#include <cuda_runtime.h>
#include <cuda_fp16.h>
#include <cstdint>
#include <math.h>

// SpatialGRU: B=256, C=128, L1=L2=32, U=128
// R14 base + regime dispatch: k1 = 128-row tiles (nc>10, throughput regime)
// or 64-row tiles (nc<=10, latency regime). k2 = 64-row tiles always.
// fp16 m16n8k16, ldmatrix, 2-stage cp.async, PDL with pre-wait MMA iters.

#define NP  1024
#define BSZ 256
#define NTHR 512

// ---- device scratch (no allocation allowed) ----
__device__ __half g_Th [NP * BSZ * 128];  // s, fp16 (MMA operand)
__device__ float  g_H  [NP * BSZ * 128];  // h, fp32 (epilogue operand)
__device__ __half g_Hr [NP * BSZ * 128];  // h, fp16 (MMA operand)
__device__ __half g_WpT[896 * 512];       // W^T col-permuted, [n][k]
__device__ __half g_U2T[128 * 512];       // [Umat;w_ij]^T, [n][k]
__device__ float  g_bP [896];             // permuted bias
__device__ __half g_A2 [8192 * 384];      // GEMM2 A (r*h parts)
__device__ float  g_Z  [8192 * 512];      // softmaxed gates [m][u*4+g]

__device__ __forceinline__ void mma16(float* c, const uint32_t* a, uint32_t b0, uint32_t b1) {
    asm volatile("mma.sync.aligned.m16n8k16.row.col.f32.f16.f16.f32 "
        "{%0,%1,%2,%3},{%4,%5,%6,%7},{%8,%9},{%0,%1,%2,%3};"
        : "+f"(c[0]), "+f"(c[1]), "+f"(c[2]), "+f"(c[3])
        : "r"(a[0]), "r"(a[1]), "r"(a[2]), "r"(a[3]), "r"(b0), "r"(b1));
}
__device__ __forceinline__ void cp16(uint32_t dst, const void* src, int sz) {
    asm volatile("cp.async.cg.shared.global [%0], [%1], 16, %2;" :: "r"(dst), "l"(src), "r"(sz));
}
__device__ __forceinline__ void ldsm4(uint32_t* r, uint32_t a) {
    asm volatile("ldmatrix.sync.aligned.m8n8.x4.shared.b16 {%0,%1,%2,%3}, [%4];"
        : "=r"(r[0]), "=r"(r[1]), "=r"(r[2]), "=r"(r[3]) : "r"(a));
}
__device__ __forceinline__ void ldsm2(uint32_t* r, uint32_t a) {
    asm volatile("ldmatrix.sync.aligned.m8n8.x2.shared.b16 {%0,%1}, [%2];"
        : "=r"(r[0]), "=r"(r[1]) : "r"(a));
}
__device__ __forceinline__ void pdl_wait() {
    asm volatile("griddepcontrol.wait;" ::: "memory");
}
__device__ __forceinline__ void pdl_trigger() {
    asm volatile("griddepcontrol.launch_dependents;" ::: "memory");
}

// ---------------------------------------------------------------------------
// setup (2 launches)
__global__ void transpose_kernel(const float* __restrict__ in) {
    __shared__ float tile[32][33];
    int x  = blockIdx.x * 32 + threadIdx.x;   // p
    int y0 = blockIdx.y * 32;                 // bc
#pragma unroll
    for (int r = 0; r < 4; r++) {
        int y = y0 + threadIdx.y + r * 8;
        tile[threadIdx.y + r * 8][threadIdx.x] = in[(size_t)y * 1024 + x];
    }
    __syncthreads();
    int xo  = blockIdx.y * 32 + threadIdx.x;
    int yo0 = blockIdx.x * 32;
#pragma unroll
    for (int r = 0; r < 4; r++) {
        int yo = yo0 + threadIdx.y + r * 8;
        g_Th[(size_t)yo * 32768 + xo] = __float2half_rn(tile[threadIdx.x][threadIdx.y + r * 8]);
    }
}

#define NWT (896 * 512)
#define NUT (128 * 512)
__global__ void prep_all_kernel(const float* __restrict__ W, const float* __restrict__ Umat,
                                const float* __restrict__ w_ij, const float* __restrict__ bias) {
    int idx = blockIdx.x * 256 + threadIdx.x;
    if (idx < NWT) {
        int n = idx >> 9, k = idx & 511;
        int corig = (n < 384) ? n : 384 + ((n - 384) & 3) * 128 + ((n - 384) >> 2);
        g_WpT[idx] = __float2half_rn(W[(size_t)k * 896 + corig]);
    } else if (idx < NWT + NUT) {
        int t = idx - NWT;
        int n = t >> 9, k = t & 511;
        g_U2T[t] = __float2half_rn((k < 384) ? Umat[k * 128 + n] : w_ij[(k - 384) * 128 + n]);
    } else if (idx < NWT + NUT + 896) {
        int c = idx - NWT - NUT;
        if (c < 384) g_bP[c] = bias[c];
        else {
            int cc = c - 384, u = cc >> 2, g = cc & 3;
            g_bP[c] = bias[384 + g * 128 + u];
        }
    }
}

// ---------------------------------------------------------------------------
#define STRH   72
// 128-row tile (k1 wide): A = 128 x 64 staged
#define AH1    (128 * STRH)
#define STG1   (2 * AH1)
#define SMEM1  (2 * STG1 * 2)           // 73728
// 64-row tile (k1s / k2): A = 64 x 64 staged
#define AH2    (64 * STRH)
#define STG2   (AH2 + 128 * STRH)
#define SMEM2  (2 * STG2 * 2)           // 55296

// 128-row MMA: 4x4 warp grid of 32x32 warp tiles
#define MMA_T1(aB_)  do {                                                       \
        const uint32_t bBv_ = (aB_) + AH1 * 2;                                  \
        _Pragma("unroll")                                                       \
        for (int k16 = 0; k16 < 4; k16++) {                                     \
            const uint32_t kb2 = k16 * 32;                                      \
            uint32_t af0[4], af1[4];                                            \
            ldsm4(af0, (aB_) + aOff0 + kb2);                                    \
            ldsm4(af1, (aB_) + aOff1 + kb2);                                    \
            _Pragma("unroll")                                                   \
            for (int nt = 0; nt < 4; nt++) {                                    \
                uint32_t bf[2];                                                 \
                ldsm2(bf, bBv_ + bOff + nt * (8 * STRH * 2) + kb2);             \
                mma16(acc[0][nt], af0, bf[0], bf[1]);                           \
                mma16(acc[1][nt], af1, bf[0], bf[1]);                           \
            }                                                                   \
        }                                                                       \
    } while (0)

// 64-row MMA: 4x4 warp grid of 16x32 warp tiles
#define MMA_T2(aB_)  do {                                                       \
        const uint32_t bBv_ = (aB_) + AH2 * 2;                                  \
        _Pragma("unroll")                                                       \
        for (int k16 = 0; k16 < 4; k16++) {                                     \
            const uint32_t kb2 = k16 * 32;                                      \
            uint32_t af[4];                                                     \
            ldsm4(af, (aB_) + aOff0 + kb2);                                     \
            _Pragma("unroll")                                                   \
            for (int nt = 0; nt < 4; nt++) {                                    \
                uint32_t bf[2];                                                 \
                ldsm2(bf, bBv_ + bOff + nt * (8 * STRH * 2) + kb2);             \
                mma16(acc[nt], af, bf[0], bf[1]);                               \
            }                                                                   \
        }                                                                       \
    } while (0)

// K1 epilogue body, shared (parameterized by per-warp row lr / acc row ptr)
__device__ __forceinline__ void k1_epi_row(int nc0, int i, int j, int p, int b0,
                                           int lr, int Mr, int wn, int qj,
                                           const float* accr) {
    if (nc0 < 384) {
        const float* hp = nullptr;
        int seg0 = nc0 >> 7;
        if (seg0 == 0)      { if (j > 0)          hp = g_H + ((size_t)(p - 1 ) * BSZ + b0) * 128; }
        else if (seg0 == 1) { if (i > 0)          hp = g_H + ((size_t)(p - 32) * BSZ + b0) * 128; }
        else                { if (i > 0 && j > 0) hp = g_H + ((size_t)(p - 33) * BSZ + b0) * 128; }
#pragma unroll
        for (int nt = 0; nt < 4; nt++) {
            int c = nc0 + wn * 32 + nt * 8 + 2 * qj;
            float v0 = accr[nt * 2 + 0] + g_bP[c];
            float v1 = accr[nt * 2 + 1] + g_bP[c + 1];
            v0 = fminf(fmaxf(0.2f * v0 + 0.5f, 0.f), 1.f);
            v1 = fminf(fmaxf(0.2f * v1 + 0.5f, 0.f), 1.f);
            int u = c & 127;
            float h0 = hp ? hp[lr * 128 + u]     : 0.f;
            float h1 = hp ? hp[lr * 128 + u + 1] : 0.f;
            *(__half2*)&g_A2[(size_t)Mr * 384 + c] = __floats2half2_rn(v0 * h0, v1 * h1);
        }
    } else {
#pragma unroll
        for (int nt = 0; nt < 4; nt++) {
            int c = nc0 + wn * 32 + nt * 8 + 2 * qj;
            float z0 = accr[nt * 2 + 0] + g_bP[c];
            float z1 = accr[nt * 2 + 1] + g_bP[c + 1];
            float q0 = __shfl_xor_sync(0xffffffffu, z0, 1);
            float q1 = __shfl_xor_sync(0xffffffffu, z1, 1);
            float mx = fmaxf(fmaxf(z0, z1), fmaxf(q0, q1));
            float e0 = __expf(z0 - mx), e1 = __expf(z1 - mx);
            float s2 = e0 + e1;
            float st = s2 + __shfl_xor_sync(0xffffffffu, s2, 1);
            float inv = 1.f / st;
            int cc = c - 384, u = cc >> 2, g = cc & 3;
            *(float2*)&g_Z[(size_t)Mr * 512 + u * 4 + g] = make_float2(e0 * inv, e1 * inv);
        }
    }
}

// NOTE: k1_epi_row expects accr laid out [nt][pair] for ONE output row; the
// callers below repack acc accordingly.

// ---------------------------------------------------------------------------
// K1 wide: 128-row tiles, grid (7, nc*2). R14-exact.
__global__ __launch_bounds__(NTHR) void k1_kernel(int d) {
    extern __shared__ __half sm[];
    const uint32_t smA0 = (uint32_t)__cvta_generic_to_shared(sm);

    const int tid = threadIdx.x, lane = tid & 31, warp = tid >> 5;
    const int wm = warp >> 2, wn = warp & 3, qj = lane & 3, ql = lane >> 2;
    const int i0 = (d > 31) ? d - 31 : 0;
    const int Mbase = blockIdx.y * 128;
    const int cell = Mbase >> 8, b0 = Mbase & 255;
    const int i = i0 + cell, j = d - i, p = i * 32 + j;
    const int nc0 = blockIdx.x * 128;

    const int l15 = lane & 15, lhi = lane >> 4;
    const uint32_t aOff0 = ((wm * 32 + l15) * STRH + lhi * 8) * 2;
    const uint32_t aOff1 = aOff0 + 16 * STRH * 2;
    const uint32_t bOff  = ((wn * 32 + (lane & 7)) * STRH + ((lane >> 3) & 1) * 8) * 2;

    const __half* src[4]; int vld[4];
    vld[0] = (i > 0) ? 16 : 0;
    vld[1] = (j > 0) ? 16 : 0;
    vld[2] = (i > 0 && j > 0) ? 16 : 0;
    vld[3] = 16;
    src[0] = vld[0] ? g_Hr + ((size_t)(p - 32) * BSZ + b0) * 128 : g_Th;
    src[1] = vld[1] ? g_Hr + ((size_t)(p - 1 ) * BSZ + b0) * 128 : g_Th;
    src[2] = vld[2] ? g_Hr + ((size_t)(p - 33) * BSZ + b0) * 128 : g_Th;
    src[3] = g_Th + ((size_t)p * BSZ + b0) * 128;

    float acc[2][4][4] = {};

#define STAGE1(t, buf) do {                                                     \
        int ps_ = (t) >> 1;                                                     \
        int seg_ = (ps_ == 0) ? 3 : ps_ - 1;                                    \
        const __half* sp_ = src[seg_]; int v_ = vld[seg_];                      \
        int kof_ = ((t) & 1) * 64;                                              \
        uint32_t aB_ = smA0 + (buf) * (STG1 * 2);                               \
        uint32_t bB_ = aB_ + AH1 * 2;                                           \
        _Pragma("unroll")                                                       \
        for (int r_ = 0; r_ < 2; r_++) {                                        \
            int ix_ = tid + r_ * NTHR;                                          \
            int m_ = ix_ >> 3, c_ = ix_ & 7;                                    \
            cp16(aB_ + (m_ * STRH + c_ * 8) * 2,                                \
                 sp_ + (size_t)m_ * 128 + kof_ + c_ * 8, v_);                   \
        }                                                                       \
        const __half* wp_ = g_WpT + (size_t)nc0 * 512 + seg_ * 128 + kof_;      \
        _Pragma("unroll")                                                       \
        for (int r_ = 0; r_ < 2; r_++) {                                        \
            int ix_ = tid + r_ * NTHR;                                          \
            int n_ = ix_ >> 3, c_ = ix_ & 7;                                    \
            cp16(bB_ + (n_ * STRH + c_ * 8) * 2,                                \
                 wp_ + (size_t)n_ * 512 + c_ * 8, 16);                          \
        }                                                                       \
        asm volatile("cp.async.commit_group;");                                 \
    } while (0)

    STAGE1(0, 0);
    STAGE1(1, 1);
    asm volatile("cp.async.wait_group 1;");
    __syncthreads();
    MMA_T1(smA0);
    asm volatile("cp.async.wait_group 0;");
    __syncthreads();
    MMA_T1(smA0 + STG1 * 2);
    pdl_wait();
    __syncthreads();
    STAGE1(2, 0);
    STAGE1(3, 1);
#pragma unroll 1
    for (int t = 2; t < 8; t++) {
        if (t < 7) asm volatile("cp.async.wait_group 1;");
        else       asm volatile("cp.async.wait_group 0;");
        __syncthreads();
        const uint32_t aB = smA0 + (t & 1) * (STG1 * 2);
        MMA_T1(aB);
        __syncthreads();
        if (t < 6) STAGE1(t + 2, t & 1);
    }
    pdl_trigger();

#pragma unroll
    for (int mt = 0; mt < 2; mt++) {
#pragma unroll
        for (int half = 0; half < 2; half++) {
            int lr = wm * 32 + mt * 16 + ql + half * 8;
            int Mr = Mbase + lr;
            float accr[8];
#pragma unroll
            for (int nt = 0; nt < 4; nt++) {
                accr[nt * 2 + 0] = acc[mt][nt][half * 2 + 0];
                accr[nt * 2 + 1] = acc[mt][nt][half * 2 + 1];
            }
            k1_epi_row(nc0, i, j, p, b0, lr, Mr, wn, qj, accr);
        }
    }
}

// ---------------------------------------------------------------------------
// K1 small: 64-row tiles, grid (7, nc*4). R15 variant (latency regime only).
__global__ __launch_bounds__(NTHR) void k1s_kernel(int d) {
    extern __shared__ __half sm[];
    const uint32_t smA0 = (uint32_t)__cvta_generic_to_shared(sm);

    const int tid = threadIdx.x, lane = tid & 31, warp = tid >> 5;
    const int wm = warp >> 2, wn = warp & 3, qj = lane & 3, ql = lane >> 2;
    const int i0 = (d > 31) ? d - 31 : 0;
    const int Mbase = blockIdx.y * 64;
    const int cell = Mbase >> 8, b0 = Mbase & 255;
    const int i = i0 + cell, j = d - i, p = i * 32 + j;
    const int nc0 = blockIdx.x * 128;

    const int l15 = lane & 15, lhi = lane >> 4;
    const uint32_t aOff0 = ((wm * 16 + l15) * STRH + lhi * 8) * 2;
    const uint32_t bOff  = ((wn * 32 + (lane & 7)) * STRH + ((lane >> 3) & 1) * 8) * 2;

    const __half* src[4]; int vld[4];
    vld[0] = (i > 0) ? 16 : 0;
    vld[1] = (j > 0) ? 16 : 0;
    vld[2] = (i > 0 && j > 0) ? 16 : 0;
    vld[3] = 16;
    src[0] = vld[0] ? g_Hr + ((size_t)(p - 32) * BSZ + b0) * 128 : g_Th;
    src[1] = vld[1] ? g_Hr + ((size_t)(p - 1 ) * BSZ + b0) * 128 : g_Th;
    src[2] = vld[2] ? g_Hr + ((size_t)(p - 33) * BSZ + b0) * 128 : g_Th;
    src[3] = g_Th + ((size_t)p * BSZ + b0) * 128;

    float acc[4][4] = {};

#define STAGE1S(t, buf) do {                                                    \
        int ps_ = (t) >> 1;                                                     \
        int seg_ = (ps_ == 0) ? 3 : ps_ - 1;                                    \
        const __half* sp_ = src[seg_]; int v_ = vld[seg_];                      \
        int kof_ = ((t) & 1) * 64;                                              \
        uint32_t aB_ = smA0 + (buf) * (STG2 * 2);                               \
        uint32_t bB_ = aB_ + AH2 * 2;                                           \
        {                                                                       \
            int m_ = tid >> 3, c_ = tid & 7;                                    \
            cp16(aB_ + (m_ * STRH + c_ * 8) * 2,                                \
                 sp_ + (size_t)m_ * 128 + kof_ + c_ * 8, v_);                   \
        }                                                                       \
        const __half* wp_ = g_WpT + (size_t)nc0 * 512 + seg_ * 128 + kof_;      \
        _Pragma("unroll")                                                       \
        for (int r_ = 0; r_ < 2; r_++) {                                        \
            int ix_ = tid + r_ * NTHR;                                          \
            int n_ = ix_ >> 3, c_ = ix_ & 7;                                    \
            cp16(bB_ + (n_ * STRH + c_ * 8) * 2,                                \
                 wp_ + (size_t)n_ * 512 + c_ * 8, 16);                          \
        }                                                                       \
        asm volatile("cp.async.commit_group;");                                 \
    } while (0)

    STAGE1S(0, 0);
    STAGE1S(1, 1);
    asm volatile("cp.async.wait_group 1;");
    __syncthreads();
    MMA_T2(smA0);
    asm volatile("cp.async.wait_group 0;");
    __syncthreads();
    MMA_T2(smA0 + STG2 * 2);
    pdl_wait();
    __syncthreads();
    STAGE1S(2, 0);
    STAGE1S(3, 1);
#pragma unroll 1
    for (int t = 2; t < 8; t++) {
        if (t < 7) asm volatile("cp.async.wait_group 1;");
        else       asm volatile("cp.async.wait_group 0;");
        __syncthreads();
        const uint32_t aB = smA0 + (t & 1) * (STG2 * 2);
        MMA_T2(aB);
        __syncthreads();
        if (t < 6) STAGE1S(t + 2, t & 1);
    }
    pdl_trigger();

#pragma unroll
    for (int half = 0; half < 2; half++) {
        int lr = wm * 16 + ql + half * 8;
        int Mr = Mbase + lr;
        float accr[8];
#pragma unroll
        for (int nt = 0; nt < 4; nt++) {
            accr[nt * 2 + 0] = acc[nt][half * 2 + 0];
            accr[nt * 2 + 1] = acc[nt][half * 2 + 1];
        }
        k1_epi_row(nc0, i, j, p, b0, lr, Mr, wn, qj, accr);
    }
}

// ---------------------------------------------------------------------------
// K2: 64-row tiles, grid nc*4 (R14-exact).
__global__ __launch_bounds__(NTHR) void k2_kernel(int d, const float* __restrict__ bias,
                                                  float* __restrict__ out) {
    extern __shared__ __half sm[];
    const uint32_t smA0 = (uint32_t)__cvta_generic_to_shared(sm);

    const int tid = threadIdx.x, lane = tid & 31, warp = tid >> 5;
    const int wm = warp >> 2, wn = warp & 3, qj = lane & 3, ql = lane >> 2;
    const int i0 = (d > 31) ? d - 31 : 0;
    const int Mbase = blockIdx.x * 64;
    const int cell = Mbase >> 8, b0 = Mbase & 255;
    const int i = i0 + cell, j = d - i, p = i * 32 + j;

    const int l15 = lane & 15, lhi = lane >> 4;
    const uint32_t aOff0 = ((wm * 16 + l15) * STRH + lhi * 8) * 2;
    const uint32_t bOff  = ((wn * 32 + (lane & 7)) * STRH + ((lane >> 3) & 1) * 8) * 2;

    const __half* Tsrc = g_Th + ((size_t)p * BSZ + b0) * 128;
    float acc[4][4] = {};

#define STAGE2(t, buf) do {                                                     \
        uint32_t aB_ = smA0 + (buf) * (STG2 * 2);                               \
        uint32_t bB_ = aB_ + AH2 * 2;                                           \
        {                                                                       \
            int m_ = tid >> 3, c_ = tid & 7;                                    \
            const __half* sp_;                                                  \
            if ((t) < 2) sp_ = Tsrc + (size_t)m_ * 128 + (t) * 64 + c_ * 8;             \
            else         sp_ = g_A2 + (size_t)(Mbase + m_) * 384 + ((t) - 2) * 64 + c_ * 8; \
            cp16(aB_ + (m_ * STRH + c_ * 8) * 2, sp_, 16);                      \
        }                                                                       \
        const __half* up_ = g_U2T + (((t) < 2) ? (384 + (t) * 64) : (((t) - 2) * 64)); \
        _Pragma("unroll")                                                       \
        for (int r_ = 0; r_ < 2; r_++) {                                        \
            int ix_ = tid + r_ * NTHR;                                          \
            int n_ = ix_ >> 3, c_ = ix_ & 7;                                    \
            cp16(bB_ + (n_ * STRH + c_ * 8) * 2,                                \
                 up_ + (size_t)n_ * 512 + c_ * 8, 16);                          \
        }                                                                       \
        asm volatile("cp.async.commit_group;");                                 \
    } while (0)

    STAGE2(0, 0);
    STAGE2(1, 1);
    asm volatile("cp.async.wait_group 1;");
    __syncthreads();
    MMA_T2(smA0);
    asm volatile("cp.async.wait_group 0;");
    __syncthreads();
    MMA_T2(smA0 + STG2 * 2);
    pdl_wait();
    __syncthreads();
    STAGE2(2, 0);
    STAGE2(3, 1);
#pragma unroll 1
    for (int t = 2; t < 8; t++) {
        if (t < 7) asm volatile("cp.async.wait_group 1;");
        else       asm volatile("cp.async.wait_group 0;");
        __syncthreads();
        const uint32_t aB = smA0 + (t & 1) * (STG2 * 2);
        MMA_T2(aB);
        __syncthreads();
        if (t < 6) STAGE2(t + 2, t & 1);
    }
    pdl_trigger();

    const float* hL = (j > 0)          ? g_H + ((size_t)(p - 1 ) * BSZ + b0) * 128 : nullptr;
    const float* hT = (i > 0)          ? g_H + ((size_t)(p - 32) * BSZ + b0) * 128 : nullptr;
    const float* hD = (i > 0 && j > 0) ? g_H + ((size_t)(p - 33) * BSZ + b0) * 128 : nullptr;
    float*  Hd  = g_H  + ((size_t)p * BSZ + b0) * 128;
    __half* Hrd = g_Hr + ((size_t)p * BSZ + b0) * 128;

#pragma unroll
    for (int half = 0; half < 2; half++) {
        int lr = wm * 16 + ql + half * 8;
        int Mr = Mbase + lr;
#pragma unroll
        for (int nt = 0; nt < 4; nt++) {
            int u = wn * 32 + nt * 8 + 2 * qj;
            float a0 = acc[nt][half * 2 + 0] + bias[896 + u];
            float a1 = acc[nt][half * 2 + 1] + bias[896 + u + 1];
            float hs0 = tanhf(a0), hs1 = tanhf(a1);
            float4 z0 = *(const float4*)&g_Z[(size_t)Mr * 512 + u * 4];
            float4 z1 = *(const float4*)&g_Z[(size_t)Mr * 512 + (u + 1) * 4];
            float l0 = hL ? hL[lr * 128 + u] : 0.f, l1 = hL ? hL[lr * 128 + u + 1] : 0.f;
            float t0 = hT ? hT[lr * 128 + u] : 0.f, t1 = hT ? hT[lr * 128 + u + 1] : 0.f;
            float d0 = hD ? hD[lr * 128 + u] : 0.f, d1 = hD ? hD[lr * 128 + u + 1] : 0.f;
            float h0 = z0.y * l0 + z0.z * t0 + z0.w * d0 + z0.x * hs0;
            float h1 = z1.y * l1 + z1.z * t1 + z1.w * d1 + z1.x * hs1;
            *(float2*)&Hd[lr * 128 + u]   = make_float2(h0, h1);
            *(__half2*)&Hrd[lr * 128 + u] = __floats2half2_rn(h0, h1);
            if (p == 1023)
                *(float2*)&out[(size_t)(b0 + lr) * 128 + u] = make_float2(h0, h1);
        }
    }
}

// ---------------------------------------------------------------------------
extern "C" void kernel_launch(void* const* d_in, const int* in_sizes, int n_in,
                              void* d_out, int out_size) {
    const float* inputs = (const float*)d_in[0];
    const float* W      = (const float*)d_in[1];
    const float* Umat   = (const float*)d_in[2];
    const float* bias   = (const float*)d_in[3];
    const float* w_ij   = (const float*)d_in[4];
    float* out = (float*)d_out;

    cudaFuncSetAttribute(k1_kernel,  cudaFuncAttributeMaxDynamicSharedMemorySize, SMEM1);
    cudaFuncSetAttribute(k1s_kernel, cudaFuncAttributeMaxDynamicSharedMemorySize, SMEM2);
    cudaFuncSetAttribute(k2_kernel,  cudaFuncAttributeMaxDynamicSharedMemorySize, SMEM2);

    transpose_kernel<<<dim3(32, 1024), dim3(32, 8)>>>(inputs);
    prep_all_kernel<<<(NWT + NUT + 896 + 255) / 256, 256>>>(W, Umat, w_ij, bias);

    cudaLaunchAttribute attrs[1];
    attrs[0].id = cudaLaunchAttributeProgrammaticStreamSerialization;
    attrs[0].val.programmaticStreamSerializationAllowed = 1;

    for (int d = 0; d <= 62; d++) {
        int i0 = (d > 31) ? d - 31 : 0;
        int i1 = (d < 31) ? d : 31;
        int nc = i1 - i0 + 1;

        if (nc <= 10) {
            // latency regime: 64-row k1 tiles
            if (d == 0) {
                k1s_kernel<<<dim3(7, nc * 4), NTHR, SMEM2>>>(d);
            } else {
                cudaLaunchConfig_t c1 = {};
                c1.gridDim = dim3(7, nc * 4); c1.blockDim = dim3(NTHR);
                c1.dynamicSmemBytes = SMEM2; c1.stream = 0;
                c1.attrs = attrs; c1.numAttrs = 1;
                cudaLaunchKernelEx(&c1, k1s_kernel, d);
            }
        } else {
            // throughput regime: 128-row k1 tiles
            cudaLaunchConfig_t c1 = {};
            c1.gridDim = dim3(7, nc * 2); c1.blockDim = dim3(NTHR);
            c1.dynamicSmemBytes = SMEM1; c1.stream = 0;
            c1.attrs = attrs; c1.numAttrs = 1;
            cudaLaunchKernelEx(&c1, k1_kernel, d);
        }
        cudaLaunchConfig_t c2 = {};
        c2.gridDim = dim3(nc * 4); c2.blockDim = dim3(NTHR);
        c2.dynamicSmemBytes = SMEM2; c2.stream = 0;
        c2.attrs = attrs; c2.numAttrs = 1;
        cudaLaunchKernelEx(&c2, k2_kernel, d, bias, out);
    }
    (void)in_sizes; (void)n_in; (void)out_size;
}

// round 17
// speedup vs baseline: 1.1139x; 1.0335x over previous
#include <cuda_runtime.h>
#include <cuda_fp16.h>
#include <cstdint>
#include <math.h>

// SpatialGRU: B=256, C=128, L1=L2=32, U=128
// R16 + k2 split to 32-row tiles (grid nc*8, 2x8 warp grid of 16x16 tiles).
// k1 regime dispatch kept: 128-row (nc>10) / 64-row (nc<=10).
// fp16 m16n8k16, ldmatrix, 2-stage cp.async, PDL with pre-wait MMA iters.

#define NP  1024
#define BSZ 256
#define NTHR 512

// ---- device scratch (no allocation allowed) ----
__device__ __half g_Th [NP * BSZ * 128];  // s, fp16 (MMA operand)
__device__ float  g_H  [NP * BSZ * 128];  // h, fp32 (epilogue operand)
__device__ __half g_Hr [NP * BSZ * 128];  // h, fp16 (MMA operand)
__device__ __half g_WpT[896 * 512];       // W^T col-permuted, [n][k]
__device__ __half g_U2T[128 * 512];       // [Umat;w_ij]^T, [n][k]
__device__ float  g_bP [896];             // permuted bias
__device__ __half g_A2 [8192 * 384];      // GEMM2 A (r*h parts)
__device__ float  g_Z  [8192 * 512];      // softmaxed gates [m][u*4+g]

__device__ __forceinline__ void mma16(float* c, const uint32_t* a, uint32_t b0, uint32_t b1) {
    asm volatile("mma.sync.aligned.m16n8k16.row.col.f32.f16.f16.f32 "
        "{%0,%1,%2,%3},{%4,%5,%6,%7},{%8,%9},{%0,%1,%2,%3};"
        : "+f"(c[0]), "+f"(c[1]), "+f"(c[2]), "+f"(c[3])
        : "r"(a[0]), "r"(a[1]), "r"(a[2]), "r"(a[3]), "r"(b0), "r"(b1));
}
__device__ __forceinline__ void cp16(uint32_t dst, const void* src, int sz) {
    asm volatile("cp.async.cg.shared.global [%0], [%1], 16, %2;" :: "r"(dst), "l"(src), "r"(sz));
}
__device__ __forceinline__ void ldsm4(uint32_t* r, uint32_t a) {
    asm volatile("ldmatrix.sync.aligned.m8n8.x4.shared.b16 {%0,%1,%2,%3}, [%4];"
        : "=r"(r[0]), "=r"(r[1]), "=r"(r[2]), "=r"(r[3]) : "r"(a));
}
__device__ __forceinline__ void ldsm2(uint32_t* r, uint32_t a) {
    asm volatile("ldmatrix.sync.aligned.m8n8.x2.shared.b16 {%0,%1}, [%2];"
        : "=r"(r[0]), "=r"(r[1]) : "r"(a));
}
__device__ __forceinline__ void pdl_wait() {
    asm volatile("griddepcontrol.wait;" ::: "memory");
}
__device__ __forceinline__ void pdl_trigger() {
    asm volatile("griddepcontrol.launch_dependents;" ::: "memory");
}

// ---------------------------------------------------------------------------
// setup (2 launches)
__global__ void transpose_kernel(const float* __restrict__ in) {
    __shared__ float tile[32][33];
    int x  = blockIdx.x * 32 + threadIdx.x;   // p
    int y0 = blockIdx.y * 32;                 // bc
#pragma unroll
    for (int r = 0; r < 4; r++) {
        int y = y0 + threadIdx.y + r * 8;
        tile[threadIdx.y + r * 8][threadIdx.x] = in[(size_t)y * 1024 + x];
    }
    __syncthreads();
    int xo  = blockIdx.y * 32 + threadIdx.x;
    int yo0 = blockIdx.x * 32;
#pragma unroll
    for (int r = 0; r < 4; r++) {
        int yo = yo0 + threadIdx.y + r * 8;
        g_Th[(size_t)yo * 32768 + xo] = __float2half_rn(tile[threadIdx.x][threadIdx.y + r * 8]);
    }
}

#define NWT (896 * 512)
#define NUT (128 * 512)
__global__ void prep_all_kernel(const float* __restrict__ W, const float* __restrict__ Umat,
                                const float* __restrict__ w_ij, const float* __restrict__ bias) {
    int idx = blockIdx.x * 256 + threadIdx.x;
    if (idx < NWT) {
        int n = idx >> 9, k = idx & 511;
        int corig = (n < 384) ? n : 384 + ((n - 384) & 3) * 128 + ((n - 384) >> 2);
        g_WpT[idx] = __float2half_rn(W[(size_t)k * 896 + corig]);
    } else if (idx < NWT + NUT) {
        int t = idx - NWT;
        int n = t >> 9, k = t & 511;
        g_U2T[t] = __float2half_rn((k < 384) ? Umat[k * 128 + n] : w_ij[(k - 384) * 128 + n]);
    } else if (idx < NWT + NUT + 896) {
        int c = idx - NWT - NUT;
        if (c < 384) g_bP[c] = bias[c];
        else {
            int cc = c - 384, u = cc >> 2, g = cc & 3;
            g_bP[c] = bias[384 + g * 128 + u];
        }
    }
}

// ---------------------------------------------------------------------------
#define STRH   72
// 128-row tile (k1 wide)
#define AH1    (128 * STRH)
#define STG1   (2 * AH1)
#define SMEM1  (2 * STG1 * 2)           // 73728
// 64-row tile (k1s)
#define AH2    (64 * STRH)
#define STG2   (AH2 + 128 * STRH)
#define SMEM2  (2 * STG2 * 2)           // 55296
// 32-row tile (k2)
#define AH3    (32 * STRH)
#define STG3   (AH3 + 128 * STRH)
#define SMEM3  (2 * STG3 * 2)           // 46080

// 128-row MMA: 4x4 warp grid of 32x32 warp tiles
#define MMA_T1(aB_)  do {                                                       \
        const uint32_t bBv_ = (aB_) + AH1 * 2;                                  \
        _Pragma("unroll")                                                       \
        for (int k16 = 0; k16 < 4; k16++) {                                     \
            const uint32_t kb2 = k16 * 32;                                      \
            uint32_t af0[4], af1[4];                                            \
            ldsm4(af0, (aB_) + aOff0 + kb2);                                    \
            ldsm4(af1, (aB_) + aOff1 + kb2);                                    \
            _Pragma("unroll")                                                   \
            for (int nt = 0; nt < 4; nt++) {                                    \
                uint32_t bf[2];                                                 \
                ldsm2(bf, bBv_ + bOff + nt * (8 * STRH * 2) + kb2);             \
                mma16(acc[0][nt], af0, bf[0], bf[1]);                           \
                mma16(acc[1][nt], af1, bf[0], bf[1]);                           \
            }                                                                   \
        }                                                                       \
    } while (0)

// 64-row MMA: 4x4 warp grid of 16x32 warp tiles
#define MMA_T2(aB_)  do {                                                       \
        const uint32_t bBv_ = (aB_) + AH2 * 2;                                  \
        _Pragma("unroll")                                                       \
        for (int k16 = 0; k16 < 4; k16++) {                                     \
            const uint32_t kb2 = k16 * 32;                                      \
            uint32_t af[4];                                                     \
            ldsm4(af, (aB_) + aOff0 + kb2);                                     \
            _Pragma("unroll")                                                   \
            for (int nt = 0; nt < 4; nt++) {                                    \
                uint32_t bf[2];                                                 \
                ldsm2(bf, bBv_ + bOff + nt * (8 * STRH * 2) + kb2);             \
                mma16(acc[nt], af, bf[0], bf[1]);                               \
            }                                                                   \
        }                                                                       \
    } while (0)

// 32-row MMA: 2x8 warp grid of 16x16 warp tiles
#define MMA_T3(aB_)  do {                                                       \
        const uint32_t bBv_ = (aB_) + AH3 * 2;                                  \
        _Pragma("unroll")                                                       \
        for (int k16 = 0; k16 < 4; k16++) {                                     \
            const uint32_t kb2 = k16 * 32;                                      \
            uint32_t af[4];                                                     \
            ldsm4(af, (aB_) + aOff0 + kb2);                                     \
            _Pragma("unroll")                                                   \
            for (int nt = 0; nt < 2; nt++) {                                    \
                uint32_t bf[2];                                                 \
                ldsm2(bf, bBv_ + bOff + nt * (8 * STRH * 2) + kb2);             \
                mma16(acc[nt], af, bf[0], bf[1]);                               \
            }                                                                   \
        }                                                                       \
    } while (0)

// K1 epilogue body (per output row)
__device__ __forceinline__ void k1_epi_row(int nc0, int i, int j, int p, int b0,
                                           int lr, int Mr, int wn, int qj,
                                           const float* accr) {
    if (nc0 < 384) {
        const float* hp = nullptr;
        int seg0 = nc0 >> 7;
        if (seg0 == 0)      { if (j > 0)          hp = g_H + ((size_t)(p - 1 ) * BSZ + b0) * 128; }
        else if (seg0 == 1) { if (i > 0)          hp = g_H + ((size_t)(p - 32) * BSZ + b0) * 128; }
        else                { if (i > 0 && j > 0) hp = g_H + ((size_t)(p - 33) * BSZ + b0) * 128; }
#pragma unroll
        for (int nt = 0; nt < 4; nt++) {
            int c = nc0 + wn * 32 + nt * 8 + 2 * qj;
            float v0 = accr[nt * 2 + 0] + g_bP[c];
            float v1 = accr[nt * 2 + 1] + g_bP[c + 1];
            v0 = fminf(fmaxf(0.2f * v0 + 0.5f, 0.f), 1.f);
            v1 = fminf(fmaxf(0.2f * v1 + 0.5f, 0.f), 1.f);
            int u = c & 127;
            float h0 = hp ? hp[lr * 128 + u]     : 0.f;
            float h1 = hp ? hp[lr * 128 + u + 1] : 0.f;
            *(__half2*)&g_A2[(size_t)Mr * 384 + c] = __floats2half2_rn(v0 * h0, v1 * h1);
        }
    } else {
#pragma unroll
        for (int nt = 0; nt < 4; nt++) {
            int c = nc0 + wn * 32 + nt * 8 + 2 * qj;
            float z0 = accr[nt * 2 + 0] + g_bP[c];
            float z1 = accr[nt * 2 + 1] + g_bP[c + 1];
            float q0 = __shfl_xor_sync(0xffffffffu, z0, 1);
            float q1 = __shfl_xor_sync(0xffffffffu, z1, 1);
            float mx = fmaxf(fmaxf(z0, z1), fmaxf(q0, q1));
            float e0 = __expf(z0 - mx), e1 = __expf(z1 - mx);
            float s2 = e0 + e1;
            float st = s2 + __shfl_xor_sync(0xffffffffu, s2, 1);
            float inv = 1.f / st;
            int cc = c - 384, u = cc >> 2, g = cc & 3;
            *(float2*)&g_Z[(size_t)Mr * 512 + u * 4 + g] = make_float2(e0 * inv, e1 * inv);
        }
    }
}

// ---------------------------------------------------------------------------
// K1 wide: 128-row tiles, grid (7, nc*2).
__global__ __launch_bounds__(NTHR) void k1_kernel(int d) {
    extern __shared__ __half sm[];
    const uint32_t smA0 = (uint32_t)__cvta_generic_to_shared(sm);

    const int tid = threadIdx.x, lane = tid & 31, warp = tid >> 5;
    const int wm = warp >> 2, wn = warp & 3, qj = lane & 3, ql = lane >> 2;
    const int i0 = (d > 31) ? d - 31 : 0;
    const int Mbase = blockIdx.y * 128;
    const int cell = Mbase >> 8, b0 = Mbase & 255;
    const int i = i0 + cell, j = d - i, p = i * 32 + j;
    const int nc0 = blockIdx.x * 128;

    const int l15 = lane & 15, lhi = lane >> 4;
    const uint32_t aOff0 = ((wm * 32 + l15) * STRH + lhi * 8) * 2;
    const uint32_t aOff1 = aOff0 + 16 * STRH * 2;
    const uint32_t bOff  = ((wn * 32 + (lane & 7)) * STRH + ((lane >> 3) & 1) * 8) * 2;

    const __half* src[4]; int vld[4];
    vld[0] = (i > 0) ? 16 : 0;
    vld[1] = (j > 0) ? 16 : 0;
    vld[2] = (i > 0 && j > 0) ? 16 : 0;
    vld[3] = 16;
    src[0] = vld[0] ? g_Hr + ((size_t)(p - 32) * BSZ + b0) * 128 : g_Th;
    src[1] = vld[1] ? g_Hr + ((size_t)(p - 1 ) * BSZ + b0) * 128 : g_Th;
    src[2] = vld[2] ? g_Hr + ((size_t)(p - 33) * BSZ + b0) * 128 : g_Th;
    src[3] = g_Th + ((size_t)p * BSZ + b0) * 128;

    float acc[2][4][4] = {};

#define STAGE1(t, buf) do {                                                     \
        int ps_ = (t) >> 1;                                                     \
        int seg_ = (ps_ == 0) ? 3 : ps_ - 1;                                    \
        const __half* sp_ = src[seg_]; int v_ = vld[seg_];                      \
        int kof_ = ((t) & 1) * 64;                                              \
        uint32_t aB_ = smA0 + (buf) * (STG1 * 2);                               \
        uint32_t bB_ = aB_ + AH1 * 2;                                           \
        _Pragma("unroll")                                                       \
        for (int r_ = 0; r_ < 2; r_++) {                                        \
            int ix_ = tid + r_ * NTHR;                                          \
            int m_ = ix_ >> 3, c_ = ix_ & 7;                                    \
            cp16(aB_ + (m_ * STRH + c_ * 8) * 2,                                \
                 sp_ + (size_t)m_ * 128 + kof_ + c_ * 8, v_);                   \
        }                                                                       \
        const __half* wp_ = g_WpT + (size_t)nc0 * 512 + seg_ * 128 + kof_;      \
        _Pragma("unroll")                                                       \
        for (int r_ = 0; r_ < 2; r_++) {                                        \
            int ix_ = tid + r_ * NTHR;                                          \
            int n_ = ix_ >> 3, c_ = ix_ & 7;                                    \
            cp16(bB_ + (n_ * STRH + c_ * 8) * 2,                                \
                 wp_ + (size_t)n_ * 512 + c_ * 8, 16);                          \
        }                                                                       \
        asm volatile("cp.async.commit_group;");                                 \
    } while (0)

    STAGE1(0, 0);
    STAGE1(1, 1);
    asm volatile("cp.async.wait_group 1;");
    __syncthreads();
    MMA_T1(smA0);
    asm volatile("cp.async.wait_group 0;");
    __syncthreads();
    MMA_T1(smA0 + STG1 * 2);
    pdl_wait();
    __syncthreads();
    STAGE1(2, 0);
    STAGE1(3, 1);
#pragma unroll 1
    for (int t = 2; t < 8; t++) {
        if (t < 7) asm volatile("cp.async.wait_group 1;");
        else       asm volatile("cp.async.wait_group 0;");
        __syncthreads();
        const uint32_t aB = smA0 + (t & 1) * (STG1 * 2);
        MMA_T1(aB);
        __syncthreads();
        if (t < 6) STAGE1(t + 2, t & 1);
    }
    pdl_trigger();

#pragma unroll
    for (int mt = 0; mt < 2; mt++) {
#pragma unroll
        for (int half = 0; half < 2; half++) {
            int lr = wm * 32 + mt * 16 + ql + half * 8;
            int Mr = Mbase + lr;
            float accr[8];
#pragma unroll
            for (int nt = 0; nt < 4; nt++) {
                accr[nt * 2 + 0] = acc[mt][nt][half * 2 + 0];
                accr[nt * 2 + 1] = acc[mt][nt][half * 2 + 1];
            }
            k1_epi_row(nc0, i, j, p, b0, lr, Mr, wn, qj, accr);
        }
    }
}

// ---------------------------------------------------------------------------
// K1 small: 64-row tiles, grid (7, nc*4).
__global__ __launch_bounds__(NTHR) void k1s_kernel(int d) {
    extern __shared__ __half sm[];
    const uint32_t smA0 = (uint32_t)__cvta_generic_to_shared(sm);

    const int tid = threadIdx.x, lane = tid & 31, warp = tid >> 5;
    const int wm = warp >> 2, wn = warp & 3, qj = lane & 3, ql = lane >> 2;
    const int i0 = (d > 31) ? d - 31 : 0;
    const int Mbase = blockIdx.y * 64;
    const int cell = Mbase >> 8, b0 = Mbase & 255;
    const int i = i0 + cell, j = d - i, p = i * 32 + j;
    const int nc0 = blockIdx.x * 128;

    const int l15 = lane & 15, lhi = lane >> 4;
    const uint32_t aOff0 = ((wm * 16 + l15) * STRH + lhi * 8) * 2;
    const uint32_t bOff  = ((wn * 32 + (lane & 7)) * STRH + ((lane >> 3) & 1) * 8) * 2;

    const __half* src[4]; int vld[4];
    vld[0] = (i > 0) ? 16 : 0;
    vld[1] = (j > 0) ? 16 : 0;
    vld[2] = (i > 0 && j > 0) ? 16 : 0;
    vld[3] = 16;
    src[0] = vld[0] ? g_Hr + ((size_t)(p - 32) * BSZ + b0) * 128 : g_Th;
    src[1] = vld[1] ? g_Hr + ((size_t)(p - 1 ) * BSZ + b0) * 128 : g_Th;
    src[2] = vld[2] ? g_Hr + ((size_t)(p - 33) * BSZ + b0) * 128 : g_Th;
    src[3] = g_Th + ((size_t)p * BSZ + b0) * 128;

    float acc[4][4] = {};

#define STAGE1S(t, buf) do {                                                    \
        int ps_ = (t) >> 1;                                                     \
        int seg_ = (ps_ == 0) ? 3 : ps_ - 1;                                    \
        const __half* sp_ = src[seg_]; int v_ = vld[seg_];                      \
        int kof_ = ((t) & 1) * 64;                                              \
        uint32_t aB_ = smA0 + (buf) * (STG2 * 2);                               \
        uint32_t bB_ = aB_ + AH2 * 2;                                           \
        {                                                                       \
            int m_ = tid >> 3, c_ = tid & 7;                                    \
            cp16(aB_ + (m_ * STRH + c_ * 8) * 2,                                \
                 sp_ + (size_t)m_ * 128 + kof_ + c_ * 8, v_);                   \
        }                                                                       \
        const __half* wp_ = g_WpT + (size_t)nc0 * 512 + seg_ * 128 + kof_;      \
        _Pragma("unroll")                                                       \
        for (int r_ = 0; r_ < 2; r_++) {                                        \
            int ix_ = tid + r_ * NTHR;                                          \
            int n_ = ix_ >> 3, c_ = ix_ & 7;                                    \
            cp16(bB_ + (n_ * STRH + c_ * 8) * 2,                                \
                 wp_ + (size_t)n_ * 512 + c_ * 8, 16);                          \
        }                                                                       \
        asm volatile("cp.async.commit_group;");                                 \
    } while (0)

    STAGE1S(0, 0);
    STAGE1S(1, 1);
    asm volatile("cp.async.wait_group 1;");
    __syncthreads();
    MMA_T2(smA0);
    asm volatile("cp.async.wait_group 0;");
    __syncthreads();
    MMA_T2(smA0 + STG2 * 2);
    pdl_wait();
    __syncthreads();
    STAGE1S(2, 0);
    STAGE1S(3, 1);
#pragma unroll 1
    for (int t = 2; t < 8; t++) {
        if (t < 7) asm volatile("cp.async.wait_group 1;");
        else       asm volatile("cp.async.wait_group 0;");
        __syncthreads();
        const uint32_t aB = smA0 + (t & 1) * (STG2 * 2);
        MMA_T2(aB);
        __syncthreads();
        if (t < 6) STAGE1S(t + 2, t & 1);
    }
    pdl_trigger();

#pragma unroll
    for (int half = 0; half < 2; half++) {
        int lr = wm * 16 + ql + half * 8;
        int Mr = Mbase + lr;
        float accr[8];
#pragma unroll
        for (int nt = 0; nt < 4; nt++) {
            accr[nt * 2 + 0] = acc[nt][half * 2 + 0];
            accr[nt * 2 + 1] = acc[nt][half * 2 + 1];
        }
        k1_epi_row(nc0, i, j, p, b0, lr, Mr, wn, qj, accr);
    }
}

// ---------------------------------------------------------------------------
// K2: 32-row tiles, grid nc*8, 2x8 warp grid of 16x16 warp tiles.
__global__ __launch_bounds__(NTHR) void k2_kernel(int d, const float* __restrict__ bias,
                                                  float* __restrict__ out) {
    extern __shared__ __half sm[];
    const uint32_t smA0 = (uint32_t)__cvta_generic_to_shared(sm);

    const int tid = threadIdx.x, lane = tid & 31, warp = tid >> 5;
    const int wm = warp >> 3, wn = warp & 7, qj = lane & 3, ql = lane >> 2;
    const int i0 = (d > 31) ? d - 31 : 0;
    const int Mbase = blockIdx.x * 32;
    const int cell = Mbase >> 8, b0 = Mbase & 255;
    const int i = i0 + cell, j = d - i, p = i * 32 + j;

    const int l15 = lane & 15, lhi = lane >> 4;
    const uint32_t aOff0 = ((wm * 16 + l15) * STRH + lhi * 8) * 2;
    const uint32_t bOff  = ((wn * 16 + (lane & 7)) * STRH + ((lane >> 3) & 1) * 8) * 2;

    const __half* Tsrc = g_Th + ((size_t)p * BSZ + b0) * 128;
    float acc[2][4] = {};

#define STAGE2(t, buf) do {                                                     \
        uint32_t aB_ = smA0 + (buf) * (STG3 * 2);                               \
        uint32_t bB_ = aB_ + AH3 * 2;                                           \
        if (tid < 256) {                                                        \
            int m_ = tid >> 3, c_ = tid & 7;                                    \
            const __half* sp_;                                                  \
            if ((t) < 2) sp_ = Tsrc + (size_t)m_ * 128 + (t) * 64 + c_ * 8;             \
            else         sp_ = g_A2 + (size_t)(Mbase + m_) * 384 + ((t) - 2) * 64 + c_ * 8; \
            cp16(aB_ + (m_ * STRH + c_ * 8) * 2, sp_, 16);                      \
        }                                                                       \
        const __half* up_ = g_U2T + (((t) < 2) ? (384 + (t) * 64) : (((t) - 2) * 64)); \
        _Pragma("unroll")                                                       \
        for (int r_ = 0; r_ < 2; r_++) {                                        \
            int ix_ = tid + r_ * NTHR;                                          \
            int n_ = ix_ >> 3, c_ = ix_ & 7;                                    \
            cp16(bB_ + (n_ * STRH + c_ * 8) * 2,                                \
                 up_ + (size_t)n_ * 512 + c_ * 8, 16);                          \
        }                                                                       \
        asm volatile("cp.async.commit_group;");                                 \
    } while (0)

    STAGE2(0, 0);
    STAGE2(1, 1);
    asm volatile("cp.async.wait_group 1;");
    __syncthreads();
    MMA_T3(smA0);
    asm volatile("cp.async.wait_group 0;");
    __syncthreads();
    MMA_T3(smA0 + STG3 * 2);
    pdl_wait();
    __syncthreads();
    STAGE2(2, 0);
    STAGE2(3, 1);
#pragma unroll 1
    for (int t = 2; t < 8; t++) {
        if (t < 7) asm volatile("cp.async.wait_group 1;");
        else       asm volatile("cp.async.wait_group 0;");
        __syncthreads();
        const uint32_t aB = smA0 + (t & 1) * (STG3 * 2);
        MMA_T3(aB);
        __syncthreads();
        if (t < 6) STAGE2(t + 2, t & 1);
    }
    pdl_trigger();

    const float* hL = (j > 0)          ? g_H + ((size_t)(p - 1 ) * BSZ + b0) * 128 : nullptr;
    const float* hT = (i > 0)          ? g_H + ((size_t)(p - 32) * BSZ + b0) * 128 : nullptr;
    const float* hD = (i > 0 && j > 0) ? g_H + ((size_t)(p - 33) * BSZ + b0) * 128 : nullptr;
    float*  Hd  = g_H  + ((size_t)p * BSZ + b0) * 128;
    __half* Hrd = g_Hr + ((size_t)p * BSZ + b0) * 128;

#pragma unroll
    for (int half = 0; half < 2; half++) {
        int lr = wm * 16 + ql + half * 8;
        int Mr = Mbase + lr;
#pragma unroll
        for (int nt = 0; nt < 2; nt++) {
            int u = wn * 16 + nt * 8 + 2 * qj;
            float a0 = acc[nt][half * 2 + 0] + bias[896 + u];
            float a1 = acc[nt][half * 2 + 1] + bias[896 + u + 1];
            float hs0 = tanhf(a0), hs1 = tanhf(a1);
            float4 z0 = *(const float4*)&g_Z[(size_t)Mr * 512 + u * 4];
            float4 z1 = *(const float4*)&g_Z[(size_t)Mr * 512 + (u + 1) * 4];
            float l0 = hL ? hL[lr * 128 + u] : 0.f, l1 = hL ? hL[lr * 128 + u + 1] : 0.f;
            float t0 = hT ? hT[lr * 128 + u] : 0.f, t1 = hT ? hT[lr * 128 + u + 1] : 0.f;
            float d0 = hD ? hD[lr * 128 + u] : 0.f, d1 = hD ? hD[lr * 128 + u + 1] : 0.f;
            float h0 = z0.y * l0 + z0.z * t0 + z0.w * d0 + z0.x * hs0;
            float h1 = z1.y * l1 + z1.z * t1 + z1.w * d1 + z1.x * hs1;
            *(float2*)&Hd[lr * 128 + u]   = make_float2(h0, h1);
            *(__half2*)&Hrd[lr * 128 + u] = __floats2half2_rn(h0, h1);
            if (p == 1023)
                *(float2*)&out[(size_t)(b0 + lr) * 128 + u] = make_float2(h0, h1);
        }
    }
}

// ---------------------------------------------------------------------------
extern "C" void kernel_launch(void* const* d_in, const int* in_sizes, int n_in,
                              void* d_out, int out_size) {
    const float* inputs = (const float*)d_in[0];
    const float* W      = (const float*)d_in[1];
    const float* Umat   = (const float*)d_in[2];
    const float* bias   = (const float*)d_in[3];
    const float* w_ij   = (const float*)d_in[4];
    float* out = (float*)d_out;

    cudaFuncSetAttribute(k1_kernel,  cudaFuncAttributeMaxDynamicSharedMemorySize, SMEM1);
    cudaFuncSetAttribute(k1s_kernel, cudaFuncAttributeMaxDynamicSharedMemorySize, SMEM2);
    cudaFuncSetAttribute(k2_kernel,  cudaFuncAttributeMaxDynamicSharedMemorySize, SMEM3);

    transpose_kernel<<<dim3(32, 1024), dim3(32, 8)>>>(inputs);
    prep_all_kernel<<<(NWT + NUT + 896 + 255) / 256, 256>>>(W, Umat, w_ij, bias);

    cudaLaunchAttribute attrs[1];
    attrs[0].id = cudaLaunchAttributeProgrammaticStreamSerialization;
    attrs[0].val.programmaticStreamSerializationAllowed = 1;

    for (int d = 0; d <= 62; d++) {
        int i0 = (d > 31) ? d - 31 : 0;
        int i1 = (d < 31) ? d : 31;
        int nc = i1 - i0 + 1;

        if (nc <= 10) {
            if (d == 0) {
                k1s_kernel<<<dim3(7, nc * 4), NTHR, SMEM2>>>(d);
            } else {
                cudaLaunchConfig_t c1 = {};
                c1.gridDim = dim3(7, nc * 4); c1.blockDim = dim3(NTHR);
                c1.dynamicSmemBytes = SMEM2; c1.stream = 0;
                c1.attrs = attrs; c1.numAttrs = 1;
                cudaLaunchKernelEx(&c1, k1s_kernel, d);
            }
        } else {
            cudaLaunchConfig_t c1 = {};
            c1.gridDim = dim3(7, nc * 2); c1.blockDim = dim3(NTHR);
            c1.dynamicSmemBytes = SMEM1; c1.stream = 0;
            c1.attrs = attrs; c1.numAttrs = 1;
            cudaLaunchKernelEx(&c1, k1_kernel, d);
        }
        cudaLaunchConfig_t c2 = {};
        c2.gridDim = dim3(nc * 8); c2.blockDim = dim3(NTHR);
        c2.dynamicSmemBytes = SMEM3; c2.stream = 0;
        c2.attrs = attrs; c2.numAttrs = 1;
        cudaLaunchKernelEx(&c2, k2_kernel, d, bias, out);
    }
    (void)in_sizes; (void)n_in; (void)out_size;
}